// round 3
// baseline (speedup 1.0000x reference)
#include <cuda_runtime.h>
#include <cstdint>
#include <cstddef>

// Problem constants (fixed by the reference)
#define BB 32
#define TT 4096
#define CC 512
#define NSTATIC 8
#define TCHUNK 16
#define NTHREADS 256
#define NBLOCKS (BB * (TT / TCHUNK))   // 8192
#define SPAD 516                       // smem row stride (floats): 4-aligned, 2-way LDS max

// Summary scratch + completion ticket (zero-init at load; kernel self-cleans).
__device__ float        g_summary[BB * CC];
__device__ unsigned int g_ticket;

// ---------------------------------------------------------------------------
// Bool-dtype sniffing via static_mask's known [1]*8 prefix.
//   0x01010101 -> u8 bool, 0x00000001 -> int32, else -> float32
// ---------------------------------------------------------------------------
__device__ __forceinline__ int sniff_bool_mode(const void* static_mask) {
    unsigned int w = *(const unsigned int*)static_mask;
    if (w == 0x01010101u) return 0;
    if (w == 0x00000001u) return 1;
    return 2;
}
__device__ __forceinline__ bool load_bool(const void* p, int i, int mode) {
    if (mode == 0) return ((const unsigned char*)p)[i] != 0;
    if (mode == 1) return ((const int*)p)[i] != 0;
    return ((const float*)p)[i] != 0.0f;
}

// ---------------------------------------------------------------------------
__global__ __launch_bounds__(NTHREADS, 6) void encoder_fused_kernel(
    const int*   __restrict__ code,
    const float* __restrict__ numeric_value,
    const float* __restrict__ time_delta,
    const void*  __restrict__ static_mask,   // dtype sniff only
    const void*  __restrict__ numeric_mask,
    const void*  __restrict__ seq_mask,
    const float* __restrict__ date_w,
    const float* __restrict__ date_b,
    const float* __restrict__ val_w,
    const float* __restrict__ val_b,
    const float* __restrict__ table,
    float*       __restrict__ out)
{
    __shared__ float s_tile[TCHUNK * SPAD];   // [t][c], 33.0 KB
    __shared__ int   s_code[TCHUNK];
    __shared__ float s_td[TCHUNK];
    __shared__ float s_nv[TCHUNK];
    __shared__ float s_nvm[TCHUNK];
    __shared__ unsigned int s_ticket;

    const int b    = blockIdx.y;
    const int t0   = blockIdx.x * TCHUNK;
    const int tid  = threadIdx.x;
    const int mode = sniff_bool_mode(static_mask);

    if (tid < TCHUNK) {
        int g = b * TT + t0 + tid;
        s_code[tid] = code[g];
        s_td[tid]   = time_delta[g];
        s_nv[tid]   = numeric_value[g];
        s_nvm[tid]  = load_bool(numeric_mask, g, mode) ? 1.0f : 0.0f;
    }
    __syncthreads();

    // Thread owns 4 consecutive channels for 8 tokens (half the chunk).
    const int tsel = tid >> 7;            // token half: 0 or 1
    const int cb   = (tid & 127) * 4;     // channel base

    const float4 dw = *(const float4*)(date_w + cb);
    const float4 db = *(const float4*)(date_b + cb);
    const float4 vw = *(const float4*)(val_w  + cb);
    const float4 vb = *(const float4*)(val_b  + cb);

    float4 sum = make_float4(0.f, 0.f, 0.f, 0.f);

    #pragma unroll
    for (int j = 0; j < 8; j++) {
        const int   t    = tsel * 8 + j;
        const float dynf = (t0 + t >= NSTATIC) ? 1.0f : 0.0f;
        const float td   = s_td[t];
        const float nv   = s_nv[t];
        const float nvm  = s_nvm[t];

        // Warp-contiguous 512B gather from the (L2-resident) code table.
        const float4 cr = __ldg((const float4*)(table + (size_t)s_code[t] * CC + cb));

        float4 e;
        e.x = fmaf(td, dw.x, db.x) * dynf + cr.x + fmaf(nv, vw.x, vb.x) * nvm;
        e.y = fmaf(td, dw.y, db.y) * dynf + cr.y + fmaf(nv, vw.y, vb.y) * nvm;
        e.z = fmaf(td, dw.z, db.z) * dynf + cr.z + fmaf(nv, vw.z, vb.z) * nvm;
        e.w = fmaf(td, dw.w, db.w) * dynf + cr.w + fmaf(nv, vw.w, vb.w) * nvm;

        *(float4*)&s_tile[t * SPAD + cb] = e;   // STS.128, conflict-free

        sum.x += e.x * dynf;  sum.y += e.y * dynf;
        sum.z += e.z * dynf;  sum.w += e.w * dynf;
    }
    __syncthreads();

    // Transposed store: 4 strided LDS.32 -> one STG.128 along t.
    // Warp covers 8 channels x 16 t = coalesced 64B segments; evict-first.
    float* outb = out + (size_t)b * CC * TT + t0;
    #pragma unroll
    for (int i = tid; i < CC * TCHUNK / 4; i += NTHREADS) {
        const int c  = i >> 2;
        const int tq = (i & 3) * 4;
        float4 v;
        v.x = s_tile[(tq + 0) * SPAD + c];
        v.y = s_tile[(tq + 1) * SPAD + c];
        v.z = s_tile[(tq + 2) * SPAD + c];
        v.w = s_tile[(tq + 3) * SPAD + c];
        __stcs((float4*)(outb + (size_t)c * TT + tq), v);
    }

    // Summary atomics only for rows that will inject.
    // use[b] <=> mask.sum >= T <=> last element of the prefix mask.
    const bool use_b = load_bool(seq_mask, b * TT + (TT - 1), mode);
    if (use_b) {
        float* gs = g_summary + b * CC + cb;
        atomicAdd(gs + 0, sum.x);
        atomicAdd(gs + 1, sum.y);
        atomicAdd(gs + 2, sum.z);
        atomicAdd(gs + 3, sum.w);
    }

    // -------- last-block injection + self-clean --------
    __syncthreads();
    if (tid == 0) {
        __threadfence();
        s_ticket = atomicAdd(&g_ticket, 1u);
    }
    __syncthreads();
    if (s_ticket == NBLOCKS - 1) {
        __threadfence();
        #pragma unroll 4
        for (int i = tid; i < BB * CC; i += NTHREADS) {
            const int bb = i >> 9;
            if (load_bool(seq_mask, bb * TT + (TT - 1), mode)) {
                out[(size_t)i * TT + NSTATIC] = g_summary[i] * (1.0f / 4088.0f);
            }
            g_summary[i] = 0.0f;
        }
        if (tid == 0) g_ticket = 0u;
    }
}

// ---------------------------------------------------------------------------
extern "C" void kernel_launch(void* const* d_in, const int* in_sizes, int n_in,
                              void* d_out, int out_size)
{
    const int*   code        = (const int*)  d_in[0];
    const float* num_val     = (const float*)d_in[1];
    const float* time_delta  = (const float*)d_in[2];
    const void*  static_mask =               d_in[3];
    const void*  num_mask    =               d_in[4];
    const void*  seq_mask    =               d_in[5];
    const float* date_w      = (const float*)d_in[6];
    const float* date_b      = (const float*)d_in[7];
    const float* val_w       = (const float*)d_in[8];
    const float* val_b       = (const float*)d_in[9];
    const float* table       = (const float*)d_in[10];
    float*       out         = (float*)d_out;

    dim3 grid(TT / TCHUNK, BB);   // (256, 32) = 8192 blocks
    encoder_fused_kernel<<<grid, NTHREADS>>>(
        code, num_val, time_delta, static_mask, num_mask, seq_mask,
        date_w, date_b, val_w, val_b, table, out);
}

// round 5
// speedup vs baseline: 1.2471x; 1.2471x over previous
#include <cuda_runtime.h>
#include <cstdint>
#include <cstddef>

// Problem constants (fixed by the reference)
#define BB 32
#define TT 4096
#define CC 512
#define NSTATIC 8
#define TCHUNK 16
#define NTHREADS 256
#define NBLOCKS (BB * (TT / TCHUNK))   // 8192
#define SPAD 516   // raw-tile row stride in floats: 2064B (16B aligned), <=2-way LDS

// Summary scratch + completion ticket (zero-init at load; kernel self-cleans).
__device__ float        g_summary[BB * CC];
__device__ unsigned int g_ticket;

// ---------------------------------------------------------------------------
// Bool-dtype sniffing via static_mask's known [1]*8 prefix.
//   0x01010101 -> u8 bool, 0x00000001 -> int32, else -> float32
// ---------------------------------------------------------------------------
__device__ __forceinline__ int sniff_bool_mode(const void* static_mask) {
    unsigned int w = *(const unsigned int*)static_mask;
    if (w == 0x01010101u) return 0;
    if (w == 0x00000001u) return 1;
    return 2;
}
__device__ __forceinline__ bool load_bool(const void* p, int i, int mode) {
    if (mode == 0) return ((const unsigned char*)p)[i] != 0;
    if (mode == 1) return ((const int*)p)[i] != 0;
    return ((const float*)p)[i] != 0.0f;
}

__device__ __forceinline__ void cp_async16(uint32_t dst_smem, const void* src) {
    asm volatile("cp.async.cg.shared.global [%0], [%1], 16;\n"
                 :: "r"(dst_smem), "l"(src) : "memory");
}

// ---------------------------------------------------------------------------
// Single fused kernel.
//  Phase 1: cp.async-stage 16 gathered code_table rows into smem (register-
//           free, 2048 x 16B in flight per block).
//  Phase 2: transpose-read + CVE fuse + STG.128 along t; summary atomics.
//  Phase 3 (last block via ticket): inject summary/4088 at t=8, self-clean.
// ---------------------------------------------------------------------------
__global__ __launch_bounds__(NTHREADS) void encoder_fused_kernel(
    const int*   __restrict__ code,
    const float* __restrict__ numeric_value,
    const float* __restrict__ time_delta,
    const void*  __restrict__ static_mask,   // dtype sniff only
    const void*  __restrict__ numeric_mask,
    const void*  __restrict__ seq_mask,
    const float* __restrict__ date_w,
    const float* __restrict__ date_b,
    const float* __restrict__ val_w,
    const float* __restrict__ val_b,
    const float* __restrict__ table,
    float*       __restrict__ out)
{
    __shared__ float s_raw[TCHUNK * SPAD];    // gathered rows, [t][c], 33.0 KB
    __shared__ unsigned int s_ticket;

    const int b    = blockIdx.y;
    const int t0   = blockIdx.x * TCHUNK;
    const int tid  = threadIdx.x;
    const int mode = sniff_bool_mode(static_mask);

    const uint32_t raw_base = (uint32_t)__cvta_generic_to_shared(s_raw);

    // ---- Phase 1: stage 16 rows (16 x 2048B = 2048 chunks of 16B) ----
    #pragma unroll
    for (int k = 0; k < 8; k++) {
        const int m     = tid + k * NTHREADS;
        const int row   = m >> 7;          // token index in chunk (warp-uniform)
        const int off16 = m & 127;         // 16B chunk within row
        const int cd    = __ldg(code + b * TT + t0 + row);
        cp_async16(raw_base + (uint32_t)(row * SPAD + off16 * 4) * 4u,
                   table + (size_t)cd * CC + off16 * 4);
    }
    asm volatile("cp.async.commit_group;\n" ::: "memory");

    // ---- Per-thread token scalars for phase 2 (overlaps the copies) ----
    // Work item j = tid + iter*256, c = j>>2, q = j&3 (q fixed per thread),
    // covering tokens t = 4q .. 4q+3.
    const int q = tid & 3;
    float tdk[4], nvk[4], nvmk[4], dynk[4];
    #pragma unroll
    for (int kk = 0; kk < 4; kk++) {
        const int tl = 4 * q + kk;
        const int g  = b * TT + t0 + tl;
        dynk[kk] = (t0 + tl >= NSTATIC) ? 1.0f : 0.0f;
        tdk[kk]  = __ldg(time_delta + g) * dynk[kk];
        nvk[kk]  = __ldg(numeric_value + g);
        nvmk[kk] = load_bool(numeric_mask, g, mode) ? 1.0f : 0.0f;
    }
    const bool use_b = load_bool(seq_mask, b * TT + (TT - 1), mode);

    asm volatile("cp.async.wait_group 0;\n" ::: "memory");
    __syncthreads();

    // ---- Phase 2: CVE fuse + transposed write-out + summary ----
    float* outb = out + (size_t)b * CC * TT + t0;
    #pragma unroll
    for (int iter = 0; iter < 8; iter++) {
        const int c = ((tid + iter * NTHREADS) >> 2);   // 0..511

        const float dw = __ldg(date_w + c);
        const float db = __ldg(date_b + c);
        const float vw = __ldg(val_w  + c);
        const float vb = __ldg(val_b  + c);

        float4 e;
        float* ep = &e.x;
        float  s  = 0.0f;
        #pragma unroll
        for (int kk = 0; kk < 4; kk++) {
            const float cr = s_raw[(4 * q + kk) * SPAD + c];
            const float v  = fmaf(tdk[kk], dw, db * dynk[kk]) + cr
                           + fmaf(nvk[kk], vw, vb) * nvmk[kk];
            ep[kk] = v;
            s += v * dynk[kk];
        }
        __stcs((float4*)(outb + (size_t)c * TT + 4 * q), e);

        if (use_b) atomicAdd(&g_summary[b * CC + c], s);
    }

    // ---- Phase 3: last-block injection + self-clean ----
    __syncthreads();
    if (tid == 0) {
        __threadfence();
        s_ticket = atomicAdd(&g_ticket, 1u);
    }
    __syncthreads();
    if (s_ticket == NBLOCKS - 1) {
        __threadfence();
        #pragma unroll 4
        for (int i = tid; i < BB * CC; i += NTHREADS) {
            const int bb = i >> 9;
            if (load_bool(seq_mask, bb * TT + (TT - 1), mode)) {
                out[(size_t)i * TT + NSTATIC] = g_summary[i] * (1.0f / 4088.0f);
            }
            g_summary[i] = 0.0f;
        }
        if (tid == 0) g_ticket = 0u;
    }
}

// ---------------------------------------------------------------------------
extern "C" void kernel_launch(void* const* d_in, const int* in_sizes, int n_in,
                              void* d_out, int out_size)
{
    const int*   code        = (const int*)  d_in[0];
    const float* num_val     = (const float*)d_in[1];
    const float* time_delta  = (const float*)d_in[2];
    const void*  static_mask =               d_in[3];
    const void*  num_mask    =               d_in[4];
    const void*  seq_mask    =               d_in[5];
    const float* date_w      = (const float*)d_in[6];
    const float* date_b      = (const float*)d_in[7];
    const float* val_w       = (const float*)d_in[8];
    const float* val_b       = (const float*)d_in[9];
    const float* table       = (const float*)d_in[10];
    float*       out         = (float*)d_out;

    dim3 grid(TT / TCHUNK, BB);   // (256, 32) = 8192 blocks
    encoder_fused_kernel<<<grid, NTHREADS>>>(
        code, num_val, time_delta, static_mask, num_mask, seq_mask,
        date_w, date_b, val_w, val_b, table, out);
}